// round 15
// baseline (speedup 1.0000x reference)
#include <cuda_runtime.h>
#include <cuda_fp16.h>
#include <math.h>

#define BATCH 64
#define CH 3
#define NIMG (BATCH*CH)     /* 192 */
#define HIMG (NIMG/2)       /* 96: images per pipeline half */
#define IMH 256
#define IMW 256
#define NB 256
#define NPIX (CH*IMH*IMW)   /* 196608 per batch */
#define RAD 5
#define KS 11

// Scratch (device globals: zero-initialized at module load; every launch
// leaves them zeroed again => allocation-free AND no zeroing kernel needed)
__device__ unsigned int d_hist[BATCH * NB * NB];        // 16 MB joint histograms
__device__ unsigned int d_py[BATCH * NB];               // marginal-y partial sums
__device__ double d_hx[BATCH];
__device__ double d_hxy[BATCH];
__device__ double d_ssim_sum[BATCH];
__device__ double d_mse_sum[BATCH];
// fp16-staged horizontally-convolved fields (125 MB total)
__device__ __half2 d_f01[NIMG * IMH * IMW];             // (conv x, conv y)
__device__ __half2 d_f23[NIMG * IMH * IMW];             // (conv x2, conv y2)
__device__ __half  d_f4 [NIMG * IMH * IMW];             // conv xy

// ---------------------------------------------------------------------------
// Kernel 1 (K_H): horizontal 11-tap pass over full rows + MI hist + MSE.
// block = 256 threads handles 4 rows of one image. grid = (IMH/4, HIMG).
// img0 selects the pipeline half. Round-11 body, measured best.
// ---------------------------------------------------------------------------
__global__ __launch_bounds__(256) void bsm_h_kernel(
    const float* __restrict__ x,
    const float* __restrict__ y,
    const float* __restrict__ win,
    int img0)
{
    const int tid = threadIdx.x;
    const int img = img0 + blockIdx.y;
    const int b   = img / CH;
    const int r0  = blockIdx.x * 4;

    __shared__ float2 sxy[4][268];
    __shared__ float g1[16];
    __shared__ double sred[8];

    // Separable 1D gaussian = row sums of the 2D window (sum(g)=1).
    if (tid < KS) {
        float s = 0.f;
        #pragma unroll
        for (int j = 0; j < KS; j++) s += win[tid * KS + j];
        g1[tid] = s;
    }
    // zero halos (image edge -> zero pad)
    if (tid < 5) {
        #pragma unroll
        for (int j = 0; j < 4; j++) {
            sxy[j][tid] = make_float2(0.f, 0.f);
            sxy[j][IMW + 5 + tid] = make_float2(0.f, 0.f);
        }
    }

    const size_t ibase = (size_t)img * (IMH * IMW);
    float mse_loc = 0.f;

    #pragma unroll
    for (int j = 0; j < 4; j++) {
        size_t base = ibase + (size_t)(r0 + j) * IMW;
        float xv = x[base + tid];
        float yv = y[base + tid];
        sxy[j][5 + tid] = make_float2(xv, yv);

        // MI binning (exact reference op order) + MSE
        float xf = (xv + 1.0f) * 0.5f;
        float yf = (yv + 1.0f) * 0.5f;
        int ix = (int)(xf * 256.0f); ix = min(max(ix, 0), NB - 1);
        int iy = (int)(yf * 256.0f); iy = min(max(iy, 0), NB - 1);
        atomicAdd(&d_hist[b * (NB * NB) + ix * NB + iy], 1u);
        float d = (xv * 0.5f + 0.5f) - (yv * 0.5f + 0.5f);
        mse_loc = fmaf(d, d, mse_loc);
    }
    __syncthreads();

    #pragma unroll
    for (int j = 0; j < 4; j++) {
        float a0 = 0.f, a1 = 0.f, a2 = 0.f, a3 = 0.f, a4 = 0.f;
        #pragma unroll
        for (int k = 0; k < KS; k++) {
            float w  = g1[k];
            float2 v = sxy[j][tid + k];     // one LDS.64
            a0 = fmaf(w, v.x, a0);
            a1 = fmaf(w, v.y, a1);
            a2 = fmaf(w, v.x * v.x, a2);
            a3 = fmaf(w, v.y * v.y, a3);
            a4 = fmaf(w, v.x * v.y, a4);
        }
        size_t o = ibase + (size_t)(r0 + j) * IMW + tid;
        d_f01[o] = __floats2half2_rn(a0, a1);
        d_f23[o] = __floats2half2_rn(a2, a3);
        d_f4[o]  = __float2half_rn(a4);
    }

    // block reduce mse -> one double atomic
    #pragma unroll
    for (int off = 16; off; off >>= 1)
        mse_loc += __shfl_down_sync(0xffffffffu, mse_loc, off);
    int lane = tid & 31, warp = tid >> 5;
    if (lane == 0) sred[warp] = (double)mse_loc;
    __syncthreads();
    if (tid == 0) {
        double m = 0.0;
        #pragma unroll
        for (int w = 0; w < 8; w++) m += sred[w];
        atomicAdd(&d_mse_sum[b], m);
    }
}

// ---------------------------------------------------------------------------
// Kernel 2 (K_V): vertical 11-tap pass + SSIM formula + reduction.
// block = 256 threads = 32 cols x 8 row-groups; each row-group -> 4 rows.
// grid = (IMW/32, IMH/32, HIMG). img0 selects the half. Round-11 body.
// ---------------------------------------------------------------------------
__global__ __launch_bounds__(256) void bsm_v_kernel(const float* __restrict__ win,
                                                    int img0)
{
    const int tid = threadIdx.x;
    const int img = img0 + blockIdx.z;
    const int b   = img / CH;

    __shared__ float g1[16];
    __shared__ double sred[8];

    if (tid < KS) {
        float s = 0.f;
        #pragma unroll
        for (int j = 0; j < KS; j++) s += win[tid * KS + j];
        g1[tid] = s;
    }
    __syncthreads();

    const int c   = tid & 31;
    const int col = blockIdx.x * 32 + c;
    const int r0  = blockIdx.y * 32 + (tid >> 5) * 4;
    const size_t ibase = (size_t)img * (IMH * IMW);

    float mu1[4], mu2[4], m11[4], m22[4], m12[4];

    // fields 0,1 (mu1, mu2)
    {
        float2 v[14];
        #pragma unroll
        for (int t = 0; t < 14; t++) {
            int rr = r0 + t - RAD;
            v[t] = (rr >= 0 && rr < IMH)
                 ? __half22float2(d_f01[ibase + (size_t)rr * IMW + col])
                 : make_float2(0.f, 0.f);
        }
        #pragma unroll
        for (int j = 0; j < 4; j++) { mu1[j] = 0.f; mu2[j] = 0.f; }
        #pragma unroll
        for (int k = 0; k < KS; k++) {
            float w = g1[k];
            #pragma unroll
            for (int j = 0; j < 4; j++) {
                mu1[j] = fmaf(w, v[j + k].x, mu1[j]);
                mu2[j] = fmaf(w, v[j + k].y, mu2[j]);
            }
        }
    }
    // fields 2,3 (m11, m22)
    {
        float2 v[14];
        #pragma unroll
        for (int t = 0; t < 14; t++) {
            int rr = r0 + t - RAD;
            v[t] = (rr >= 0 && rr < IMH)
                 ? __half22float2(d_f23[ibase + (size_t)rr * IMW + col])
                 : make_float2(0.f, 0.f);
        }
        #pragma unroll
        for (int j = 0; j < 4; j++) { m11[j] = 0.f; m22[j] = 0.f; }
        #pragma unroll
        for (int k = 0; k < KS; k++) {
            float w = g1[k];
            #pragma unroll
            for (int j = 0; j < 4; j++) {
                m11[j] = fmaf(w, v[j + k].x, m11[j]);
                m22[j] = fmaf(w, v[j + k].y, m22[j]);
            }
        }
    }
    // field 4 (m12)
    {
        float v[14];
        #pragma unroll
        for (int t = 0; t < 14; t++) {
            int rr = r0 + t - RAD;
            v[t] = (rr >= 0 && rr < IMH)
                 ? __half2float(d_f4[ibase + (size_t)rr * IMW + col]) : 0.f;
        }
        #pragma unroll
        for (int j = 0; j < 4; j++) m12[j] = 0.f;
        #pragma unroll
        for (int k = 0; k < KS; k++) {
            float w = g1[k];
            #pragma unroll
            for (int j = 0; j < 4; j++)
                m12[j] = fmaf(w, v[j + k], m12[j]);
        }
    }

    const float C1c = 0.01f * 0.01f;
    const float C2c = 0.03f * 0.03f;
    float ssim_loc = 0.f;
    #pragma unroll
    for (int j = 0; j < 4; j++) {
        float mu1s = mu1[j] * mu1[j];
        float mu2s = mu2[j] * mu2[j];
        float mu12 = mu1[j] * mu2[j];
        float s1  = m11[j] - mu1s;
        float s2  = m22[j] - mu2s;
        float s12 = m12[j] - mu12;
        float num = (2.f * mu12 + C1c) * (2.f * s12 + C2c);
        float den = (mu1s + mu2s + C1c) * (s1 + s2 + C2c);
        ssim_loc += num / den;
    }

    #pragma unroll
    for (int off = 16; off; off >>= 1)
        ssim_loc += __shfl_down_sync(0xffffffffu, ssim_loc, off);
    int lane = tid & 31, warp = tid >> 5;
    if (lane == 0) sred[warp] = (double)ssim_loc;
    __syncthreads();
    if (tid == 0) {
        double s = 0.0;
        #pragma unroll
        for (int w = 0; w < 8; w++) s += sred[w];
        atomicAdd(&d_ssim_sum[b], s);
    }
}

// ---------------------------------------------------------------------------
// Kernel 3a: histogram scan — coalesced uint4 reads, self-cleaning.
// Needs the COMPLETE histogram (both K_H halves); runs concurrent with KV1.
// grid = (8 chunks, 64 batches), block = 256 (8 warps, warp -> 4 rows).
// ---------------------------------------------------------------------------
__global__ __launch_bounds__(256) void bsm_fin_a_kernel()
{
    const int b     = blockIdx.y;
    const int chunk = blockIdx.x;
    const int tid   = threadIdx.x;
    const int lane  = tid & 31;
    const int warp  = tid >> 5;

    __shared__ unsigned int spy[NB];
    __shared__ double sredA[8], sredB[8];

    spy[tid] = 0u;
    __syncthreads();

    uint4* hb4 = (uint4*)&d_hist[b * NB * NB];
    const float invNf = 1.0f / (float)NPIX;
    const uint4 z4 = make_uint4(0u, 0u, 0u, 0u);

    double hxy_loc = 0.0;
    double hx_loc  = 0.0;

    // warp handles 4 consecutive rows
    #pragma unroll
    for (int rr = 0; rr < 4; rr++) {
        int row = chunk * 32 + warp * 4 + rr;
        uint4 q0 = hb4[row * 64 + lane];
        uint4 q1 = hb4[row * 64 + 32 + lane];
        hb4[row * 64 + lane] = z4;          // self-clean for next launch
        hb4[row * 64 + 32 + lane] = z4;
        unsigned int cs[8] = {q0.x, q0.y, q0.z, q0.w, q1.x, q1.y, q1.z, q1.w};

        unsigned int px_part = 0;
        float h_part = 0.f;      // Σ -p*log2(p) over this lane's 8 bins
        #pragma unroll
        for (int k = 0; k < 8; k++) {
            unsigned int cnt = cs[k];
            px_part += cnt;
            if (cnt) {
                float p = (float)cnt * invNf;
                h_part -= p * __log2f(p);
                int colk = (k < 4) ? (lane * 4 + k) : (128 + lane * 4 + (k - 4));
                atomicAdd(&spy[colk], cnt);
            }
        }
        hxy_loc += (double)h_part;

        #pragma unroll
        for (int off = 16; off; off >>= 1)
            px_part += __shfl_down_sync(0xffffffffu, px_part, off);
        if (lane == 0 && px_part) {
            float pxn = (float)px_part * invNf;
            hx_loc -= (double)(pxn * __log2f(pxn));
        }
    }

    #pragma unroll
    for (int off = 16; off; off >>= 1)
        hxy_loc += __shfl_down_sync(0xffffffffu, hxy_loc, off);
    if (lane == 0) { sredA[warp] = hxy_loc; sredB[warp] = hx_loc; }
    __syncthreads();
    if (tid == 0) {
        double a = 0.0, bb = 0.0;
        #pragma unroll
        for (int w = 0; w < 8; w++) { a += sredA[w]; bb += sredB[w]; }
        atomicAdd(&d_hxy[b], a);
        atomicAdd(&d_hx[b],  bb);
    }
    __syncthreads();
    if (spy[tid]) atomicAdd(&d_py[b * NB + tid], spy[tid]);
}

// ---------------------------------------------------------------------------
// Kernel 3b: combine — H(Y) from d_py, final MI/SSIM/PSNR, write out.
// Warp-shuffle reduction; self-cleaning. Runs at the stream join.
// ---------------------------------------------------------------------------
__global__ __launch_bounds__(256) void bsm_fin_b_kernel(float* __restrict__ out)
{
    const int b    = blockIdx.x;
    const int t    = threadIdx.x;
    const int lane = t & 31;
    const int warp = t >> 5;
    const float invNf = 1.0f / (float)NPIX;
    const double invN = 1.0 / (double)NPIX;

    __shared__ double shy[8];

    unsigned int py = d_py[b * NB + t];
    d_py[b * NB + t] = 0u;                   // self-clean
    float pyn = (float)py * invNf;
    double hy_loc = (py > 0) ? (double)(-pyn * __log2f(pyn)) : 0.0;
    #pragma unroll
    for (int off = 16; off; off >>= 1)
        hy_loc += __shfl_down_sync(0xffffffffu, hy_loc, off);
    if (lane == 0) shy[warp] = hy_loc;
    __syncthreads();

    if (t == 0) {
        double hy = 0.0;
        #pragma unroll
        for (int w = 0; w < 8; w++) hy += shy[w];

        double hx = d_hx[b], hxyv = d_hxy[b];
        double ssim_s = d_ssim_sum[b];
        double mse_s  = d_mse_sum[b];
        d_hx[b] = 0.0; d_hxy[b] = 0.0;       // self-clean
        d_ssim_sum[b] = 0.0; d_mse_sum[b] = 0.0;

        double mi = hx + hy - hxyv;
        double norm = fmin(hx, hy);
        mi = (norm > 0.0) ? (mi / norm) : 0.0;
        mi = fmin(fmax(mi, 0.0), 1.0);

        double ssim = ssim_s * invN;

        double mse = mse_s * invN;
        double psnr = (mse == 0.0) ? 100.0 : (-10.0 * log10(mse));
        psnr /= 40.0;

        out[b * 3 + 0] = (float)mi;
        out[b * 3 + 1] = (float)ssim;
        out[b * 3 + 2] = (float)psnr;
    }
}

// ---------------------------------------------------------------------------
// Launch topology (two-half software pipeline, graph-capturable):
//   s0:  KH0 ─evA─ KH1 ─evC─ KV1 ────────────────────┬─ fin_b
//   s1:    └(wait evA) KV0 ────────────────evB0──────┤
//   s2:              └(wait evC) fin_a ────evB2──────┘
// KV0 overlaps KH1; fin_a overlaps KV1.
// ---------------------------------------------------------------------------
extern "C" void kernel_launch(void* const* d_in, const int* in_sizes, int n_in,
                              void* d_out, int out_size)
{
    const float* x   = (const float*)d_in[0];
    const float* y   = (const float*)d_in[1];
    const float* win = (const float*)d_in[2];
    float* out = (float*)d_out;

    static cudaStream_t s1 = nullptr, s2 = nullptr;
    static cudaEvent_t  evA = nullptr, evC = nullptr, evB0 = nullptr, evB2 = nullptr;
    if (s1 == nullptr) {
        cudaStreamCreateWithFlags(&s1, cudaStreamNonBlocking);
        cudaStreamCreateWithFlags(&s2, cudaStreamNonBlocking);
        cudaEventCreateWithFlags(&evA,  cudaEventDisableTiming);
        cudaEventCreateWithFlags(&evC,  cudaEventDisableTiming);
        cudaEventCreateWithFlags(&evB0, cudaEventDisableTiming);
        cudaEventCreateWithFlags(&evB2, cudaEventDisableTiming);
    }

    dim3 gh(IMH / 4, HIMG);
    dim3 gv(IMW / 32, IMH / 32, HIMG);
    dim3 gf(8, BATCH);

    // s0: KH half 0
    bsm_h_kernel<<<gh, 256>>>(x, y, win, 0);
    cudaEventRecord(evA, 0);

    // s1: KV half 0 (overlaps KH half 1)
    cudaStreamWaitEvent(s1, evA, 0);
    bsm_v_kernel<<<gv, 256, 0, s1>>>(win, 0);
    cudaEventRecord(evB0, s1);

    // s0: KH half 1
    bsm_h_kernel<<<gh, 256>>>(x, y, win, HIMG);
    cudaEventRecord(evC, 0);

    // s2: fin_a (needs full histogram; overlaps KV half 1)
    cudaStreamWaitEvent(s2, evC, 0);
    bsm_fin_a_kernel<<<gf, 256, 0, s2>>>();
    cudaEventRecord(evB2, s2);

    // s0: KV half 1
    bsm_v_kernel<<<gv, 256>>>(win, HIMG);

    // join: fin_b needs fin_a, KV0, KV1 (in-order), KH (in-order)
    cudaStreamWaitEvent(0, evB0, 0);
    cudaStreamWaitEvent(0, evB2, 0);
    bsm_fin_b_kernel<<<BATCH, 256>>>(out);
}

// round 16
// speedup vs baseline: 1.0907x; 1.0907x over previous
#include <cuda_runtime.h>
#include <cuda_fp16.h>
#include <math.h>

#define BATCH 64
#define CH 3
#define NIMG (BATCH*CH)     /* 192 */
#define IMH 256
#define IMW 256
#define NB 256
#define NPIX (CH*IMH*IMW)   /* 196608 per batch */
#define RAD 5
#define KS 11

// Scratch (device globals: zero-initialized at module load; every launch
// leaves them zeroed again => allocation-free AND no zeroing kernel needed)
__device__ unsigned int d_hist[BATCH * NB * NB];        // 16 MB joint histograms
__device__ unsigned int d_py[BATCH * NB];               // marginal-y partial sums
__device__ double d_hx[BATCH];
__device__ double d_hxy[BATCH];
__device__ double d_ssim_sum[BATCH];
__device__ double d_mse_sum[BATCH];
// fp16-staged horizontally-convolved fields (125 MB total)
__device__ __half2 d_f01[NIMG * IMH * IMW];             // (conv x, conv y)
__device__ __half2 d_f23[NIMG * IMH * IMW];             // (conv x2, conv y2)
__device__ __half  d_f4 [NIMG * IMH * IMW];             // conv xy

// ---------------------------------------------------------------------------
// Kernel 1 (K_H): horizontal 11-tap pass over full rows + MI hist + MSE.
// block = 256 threads handles 4 rows of one image. grid = (IMH/4, NIMG).
// (x,y) interleaved float2 tile — round-11/14 body, measured best.
// ---------------------------------------------------------------------------
__global__ __launch_bounds__(256) void bsm_h_kernel(
    const float* __restrict__ x,
    const float* __restrict__ y,
    const float* __restrict__ win)
{
    const int tid = threadIdx.x;
    const int img = blockIdx.y;
    const int b   = img / CH;
    const int r0  = blockIdx.x * 4;

    __shared__ float2 sxy[4][268];
    __shared__ float g1[16];
    __shared__ double sred[8];

    // Separable 1D gaussian = row sums of the 2D window (sum(g)=1).
    if (tid < KS) {
        float s = 0.f;
        #pragma unroll
        for (int j = 0; j < KS; j++) s += win[tid * KS + j];
        g1[tid] = s;
    }
    // zero halos (image edge -> zero pad)
    if (tid < 5) {
        #pragma unroll
        for (int j = 0; j < 4; j++) {
            sxy[j][tid] = make_float2(0.f, 0.f);
            sxy[j][IMW + 5 + tid] = make_float2(0.f, 0.f);
        }
    }

    const size_t ibase = (size_t)img * (IMH * IMW);
    float mse_loc = 0.f;

    #pragma unroll
    for (int j = 0; j < 4; j++) {
        size_t base = ibase + (size_t)(r0 + j) * IMW;
        float xv = x[base + tid];
        float yv = y[base + tid];
        sxy[j][5 + tid] = make_float2(xv, yv);

        // MI binning (exact reference op order) + MSE
        float xf = (xv + 1.0f) * 0.5f;
        float yf = (yv + 1.0f) * 0.5f;
        int ix = (int)(xf * 256.0f); ix = min(max(ix, 0), NB - 1);
        int iy = (int)(yf * 256.0f); iy = min(max(iy, 0), NB - 1);
        atomicAdd(&d_hist[b * (NB * NB) + ix * NB + iy], 1u);
        float d = (xv * 0.5f + 0.5f) - (yv * 0.5f + 0.5f);
        mse_loc = fmaf(d, d, mse_loc);
    }
    __syncthreads();

    #pragma unroll
    for (int j = 0; j < 4; j++) {
        float a0 = 0.f, a1 = 0.f, a2 = 0.f, a3 = 0.f, a4 = 0.f;
        #pragma unroll
        for (int k = 0; k < KS; k++) {
            float w  = g1[k];
            float2 v = sxy[j][tid + k];     // one LDS.64
            a0 = fmaf(w, v.x, a0);
            a1 = fmaf(w, v.y, a1);
            a2 = fmaf(w, v.x * v.x, a2);
            a3 = fmaf(w, v.y * v.y, a3);
            a4 = fmaf(w, v.x * v.y, a4);
        }
        size_t o = ibase + (size_t)(r0 + j) * IMW + tid;
        d_f01[o] = __floats2half2_rn(a0, a1);
        d_f23[o] = __floats2half2_rn(a2, a3);
        d_f4[o]  = __float2half_rn(a4);
    }

    // block reduce mse -> one double atomic
    #pragma unroll
    for (int off = 16; off; off >>= 1)
        mse_loc += __shfl_down_sync(0xffffffffu, mse_loc, off);
    int lane = tid & 31, warp = tid >> 5;
    if (lane == 0) sred[warp] = (double)mse_loc;
    __syncthreads();
    if (tid == 0) {
        double m = 0.0;
        #pragma unroll
        for (int w = 0; w < 8; w++) m += sred[w];
        atomicAdd(&d_mse_sum[b], m);
    }
}

// ---------------------------------------------------------------------------
// K_V body, templated on GUARD. Interior row-tiles (blockIdx.y 1..6) never
// touch rows outside [0,256) — they take the branch-free path.
// Returns this thread's ssim partial.
// ---------------------------------------------------------------------------
template <bool GUARD>
__device__ __forceinline__ float bsm_v_body(
    const float* __restrict__ wreg, int col, int r0, size_t ibase)
{
    float mu1[4], mu2[4], m11[4], m22[4], m12[4];

    // fields 0,1 (mu1, mu2)
    {
        float2 v[14];
        #pragma unroll
        for (int t = 0; t < 14; t++) {
            int rr = r0 + t - RAD;
            if (GUARD) {
                v[t] = (rr >= 0 && rr < IMH)
                     ? __half22float2(d_f01[ibase + (size_t)rr * IMW + col])
                     : make_float2(0.f, 0.f);
            } else {
                v[t] = __half22float2(d_f01[ibase + (size_t)rr * IMW + col]);
            }
        }
        #pragma unroll
        for (int j = 0; j < 4; j++) { mu1[j] = 0.f; mu2[j] = 0.f; }
        #pragma unroll
        for (int k = 0; k < KS; k++) {
            float w = wreg[k];
            #pragma unroll
            for (int j = 0; j < 4; j++) {
                mu1[j] = fmaf(w, v[j + k].x, mu1[j]);
                mu2[j] = fmaf(w, v[j + k].y, mu2[j]);
            }
        }
    }
    // fields 2,3 (m11, m22)
    {
        float2 v[14];
        #pragma unroll
        for (int t = 0; t < 14; t++) {
            int rr = r0 + t - RAD;
            if (GUARD) {
                v[t] = (rr >= 0 && rr < IMH)
                     ? __half22float2(d_f23[ibase + (size_t)rr * IMW + col])
                     : make_float2(0.f, 0.f);
            } else {
                v[t] = __half22float2(d_f23[ibase + (size_t)rr * IMW + col]);
            }
        }
        #pragma unroll
        for (int j = 0; j < 4; j++) { m11[j] = 0.f; m22[j] = 0.f; }
        #pragma unroll
        for (int k = 0; k < KS; k++) {
            float w = wreg[k];
            #pragma unroll
            for (int j = 0; j < 4; j++) {
                m11[j] = fmaf(w, v[j + k].x, m11[j]);
                m22[j] = fmaf(w, v[j + k].y, m22[j]);
            }
        }
    }
    // field 4 (m12)
    {
        float v[14];
        #pragma unroll
        for (int t = 0; t < 14; t++) {
            int rr = r0 + t - RAD;
            if (GUARD) {
                v[t] = (rr >= 0 && rr < IMH)
                     ? __half2float(d_f4[ibase + (size_t)rr * IMW + col]) : 0.f;
            } else {
                v[t] = __half2float(d_f4[ibase + (size_t)rr * IMW + col]);
            }
        }
        #pragma unroll
        for (int j = 0; j < 4; j++) m12[j] = 0.f;
        #pragma unroll
        for (int k = 0; k < KS; k++) {
            float w = wreg[k];
            #pragma unroll
            for (int j = 0; j < 4; j++)
                m12[j] = fmaf(w, v[j + k], m12[j]);
        }
    }

    const float C1c = 0.01f * 0.01f;
    const float C2c = 0.03f * 0.03f;
    float ssim_loc = 0.f;
    #pragma unroll
    for (int j = 0; j < 4; j++) {
        float mu1s = mu1[j] * mu1[j];
        float mu2s = mu2[j] * mu2[j];
        float mu12 = mu1[j] * mu2[j];
        float s1  = m11[j] - mu1s;
        float s2  = m22[j] - mu2s;
        float s12 = m12[j] - mu12;
        float num = (2.f * mu12 + C1c) * (2.f * s12 + C2c);
        float den = (mu1s + mu2s + C1c) * (s1 + s2 + C2c);
        ssim_loc += num / den;
    }
    return ssim_loc;
}

// ---------------------------------------------------------------------------
// Kernel 2 (K_V): vertical 11-tap pass + SSIM formula + reduction.
// block = 256 threads = 32 cols x 8 row-groups; each row-group -> 4 rows.
// grid = (IMW/32, IMH/32, NIMG). Interior tiles take a branch-free path.
// ---------------------------------------------------------------------------
__global__ __launch_bounds__(256) void bsm_v_kernel(const float* __restrict__ win)
{
    const int tid = threadIdx.x;
    const int img = blockIdx.z;
    const int b   = img / CH;

    __shared__ float g1[16];
    __shared__ double sred[8];

    if (tid < KS) {
        float s = 0.f;
        #pragma unroll
        for (int j = 0; j < KS; j++) s += win[tid * KS + j];
        g1[tid] = s;
    }
    __syncthreads();

    // hoist weights into registers (one LDS each instead of 3 re-reads)
    float wreg[KS];
    #pragma unroll
    for (int k = 0; k < KS; k++) wreg[k] = g1[k];

    const int c   = tid & 31;
    const int col = blockIdx.x * 32 + c;
    const int r0  = blockIdx.y * 32 + (tid >> 5) * 4;
    const size_t ibase = (size_t)img * (IMH * IMW);

    float ssim_loc;
    if (blockIdx.y == 0 || blockIdx.y == gridDim.y - 1)
        ssim_loc = bsm_v_body<true >(wreg, col, r0, ibase);
    else
        ssim_loc = bsm_v_body<false>(wreg, col, r0, ibase);

    #pragma unroll
    for (int off = 16; off; off >>= 1)
        ssim_loc += __shfl_down_sync(0xffffffffu, ssim_loc, off);
    int lane = tid & 31, warp = tid >> 5;
    if (lane == 0) sred[warp] = (double)ssim_loc;
    __syncthreads();
    if (tid == 0) {
        double s = 0.0;
        #pragma unroll
        for (int w = 0; w < 8; w++) s += sred[w];
        atomicAdd(&d_ssim_sum[b], s);
    }
}

// ---------------------------------------------------------------------------
// Kernel 3a: histogram scan — coalesced uint4 reads, self-cleaning.
// Runs on a SIDE STREAM concurrent with K_V (depends only on d_hist).
// grid = (8 chunks, 64 batches), block = 256 (8 warps, warp -> 4 rows).
// ---------------------------------------------------------------------------
__global__ __launch_bounds__(256) void bsm_fin_a_kernel()
{
    const int b     = blockIdx.y;
    const int chunk = blockIdx.x;
    const int tid   = threadIdx.x;
    const int lane  = tid & 31;
    const int warp  = tid >> 5;

    __shared__ unsigned int spy[NB];
    __shared__ double sredA[8], sredB[8];

    spy[tid] = 0u;
    __syncthreads();

    uint4* hb4 = (uint4*)&d_hist[b * NB * NB];
    const float invNf = 1.0f / (float)NPIX;
    const uint4 z4 = make_uint4(0u, 0u, 0u, 0u);

    double hxy_loc = 0.0;
    double hx_loc  = 0.0;

    // warp handles 4 consecutive rows
    #pragma unroll
    for (int rr = 0; rr < 4; rr++) {
        int row = chunk * 32 + warp * 4 + rr;
        uint4 q0 = hb4[row * 64 + lane];
        uint4 q1 = hb4[row * 64 + 32 + lane];
        hb4[row * 64 + lane] = z4;          // self-clean for next launch
        hb4[row * 64 + 32 + lane] = z4;
        unsigned int cs[8] = {q0.x, q0.y, q0.z, q0.w, q1.x, q1.y, q1.z, q1.w};

        unsigned int px_part = 0;
        float h_part = 0.f;      // Σ -p*log2(p) over this lane's 8 bins
        #pragma unroll
        for (int k = 0; k < 8; k++) {
            unsigned int cnt = cs[k];
            px_part += cnt;
            if (cnt) {
                float p = (float)cnt * invNf;
                h_part -= p * __log2f(p);
                int colk = (k < 4) ? (lane * 4 + k) : (128 + lane * 4 + (k - 4));
                atomicAdd(&spy[colk], cnt);
            }
        }
        hxy_loc += (double)h_part;

        #pragma unroll
        for (int off = 16; off; off >>= 1)
            px_part += __shfl_down_sync(0xffffffffu, px_part, off);
        if (lane == 0 && px_part) {
            float pxn = (float)px_part * invNf;
            hx_loc -= (double)(pxn * __log2f(pxn));
        }
    }

    #pragma unroll
    for (int off = 16; off; off >>= 1)
        hxy_loc += __shfl_down_sync(0xffffffffu, hxy_loc, off);
    if (lane == 0) { sredA[warp] = hxy_loc; sredB[warp] = hx_loc; }
    __syncthreads();
    if (tid == 0) {
        double a = 0.0, bb = 0.0;
        #pragma unroll
        for (int w = 0; w < 8; w++) { a += sredA[w]; bb += sredB[w]; }
        atomicAdd(&d_hxy[b], a);
        atomicAdd(&d_hx[b],  bb);
    }
    __syncthreads();
    if (spy[tid]) atomicAdd(&d_py[b * NB + tid], spy[tid]);
}

// ---------------------------------------------------------------------------
// Kernel 3b: combine — H(Y) from d_py, final MI/SSIM/PSNR, write out.
// Warp-shuffle reduction; self-cleaning. Runs at the stream join.
// ---------------------------------------------------------------------------
__global__ __launch_bounds__(256) void bsm_fin_b_kernel(float* __restrict__ out)
{
    const int b    = blockIdx.x;
    const int t    = threadIdx.x;
    const int lane = t & 31;
    const int warp = t >> 5;
    const float invNf = 1.0f / (float)NPIX;
    const double invN = 1.0 / (double)NPIX;

    __shared__ double shy[8];

    unsigned int py = d_py[b * NB + t];
    d_py[b * NB + t] = 0u;                   // self-clean
    float pyn = (float)py * invNf;
    double hy_loc = (py > 0) ? (double)(-pyn * __log2f(pyn)) : 0.0;
    #pragma unroll
    for (int off = 16; off; off >>= 1)
        hy_loc += __shfl_down_sync(0xffffffffu, hy_loc, off);
    if (lane == 0) shy[warp] = hy_loc;
    __syncthreads();

    if (t == 0) {
        double hy = 0.0;
        #pragma unroll
        for (int w = 0; w < 8; w++) hy += shy[w];

        double hx = d_hx[b], hxyv = d_hxy[b];
        double ssim_s = d_ssim_sum[b];
        double mse_s  = d_mse_sum[b];
        d_hx[b] = 0.0; d_hxy[b] = 0.0;       // self-clean
        d_ssim_sum[b] = 0.0; d_mse_sum[b] = 0.0;

        double mi = hx + hy - hxyv;
        double norm = fmin(hx, hy);
        mi = (norm > 0.0) ? (mi / norm) : 0.0;
        mi = fmin(fmax(mi, 0.0), 1.0);

        double ssim = ssim_s * invN;

        double mse = mse_s * invN;
        double psnr = (mse == 0.0) ? 100.0 : (-10.0 * log10(mse));
        psnr /= 40.0;

        out[b * 3 + 0] = (float)mi;
        out[b * 3 + 1] = (float)ssim;
        out[b * 3 + 2] = (float)psnr;
    }
}

// ---------------------------------------------------------------------------
// Launch topology (round-14 fork-join, measured best):
//   stream0: K_H ──evA──────────── K_V ────────┬── fin_b
//   side:         └─(wait evA) fin_a ───evB────┘
// ---------------------------------------------------------------------------
extern "C" void kernel_launch(void* const* d_in, const int* in_sizes, int n_in,
                              void* d_out, int out_size)
{
    const float* x   = (const float*)d_in[0];
    const float* y   = (const float*)d_in[1];
    const float* win = (const float*)d_in[2];
    float* out = (float*)d_out;

    static cudaStream_t s_side = nullptr;
    static cudaEvent_t  evA = nullptr, evB = nullptr;
    if (s_side == nullptr) {
        cudaStreamCreateWithFlags(&s_side, cudaStreamNonBlocking);
        cudaEventCreateWithFlags(&evA, cudaEventDisableTiming);
        cudaEventCreateWithFlags(&evB, cudaEventDisableTiming);
    }

    dim3 gh(IMH / 4, NIMG);
    bsm_h_kernel<<<gh, 256>>>(x, y, win);

    // fork: fin_a on side stream, concurrent with K_V
    cudaEventRecord(evA, 0);
    cudaStreamWaitEvent(s_side, evA, 0);
    dim3 gf(8, BATCH);
    bsm_fin_a_kernel<<<gf, 256, 0, s_side>>>();

    dim3 gv(IMW / 32, IMH / 32, NIMG);
    bsm_v_kernel<<<gv, 256>>>(win);

    // join: fin_b needs fin_a (hx/hxy/py) and K_V (ssim) and K_H (mse)
    cudaEventRecord(evB, s_side);
    cudaStreamWaitEvent(0, evB, 0);
    bsm_fin_b_kernel<<<BATCH, 256>>>(out);
}

// round 17
// speedup vs baseline: 1.0989x; 1.0075x over previous
#include <cuda_runtime.h>
#include <cuda_fp16.h>
#include <math.h>

#define BATCH 64
#define CH 3
#define NIMG (BATCH*CH)     /* 192 */
#define IMH 256
#define IMW 256
#define NB 256
#define NPIX (CH*IMH*IMW)   /* 196608 per batch */
#define RAD 5
#define KS 11

// Scratch (device globals: zero-initialized at module load; every launch
// leaves them zeroed again => allocation-free AND no zeroing kernel needed)
__device__ unsigned int d_hist[BATCH * NB * NB];        // 16 MB joint histograms
__device__ unsigned int d_py[BATCH * NB];               // marginal-y partial sums
__device__ double d_hx[BATCH];
__device__ double d_hxy[BATCH];
__device__ double d_ssim_sum[BATCH];
__device__ double d_mse_sum[BATCH];
// fp16-staged horizontally-convolved fields (125 MB total)
__device__ __half2 d_f01[NIMG * IMH * IMW];             // (conv x, conv y)
__device__ __half2 d_f23[NIMG * IMH * IMW];             // (conv x2, conv y2)
__device__ __half  d_f4 [NIMG * IMH * IMW];             // conv xy

// ---------------------------------------------------------------------------
// Kernel 1 (K_H): horizontal 11-tap pass over full rows + MI hist + MSE.
// block = 256 threads handles 4 rows of one image. grid = (IMH/4, NIMG).
// (x,y) interleaved float2 tile; weights register-hoisted (round-16 pattern).
// ---------------------------------------------------------------------------
__global__ __launch_bounds__(256) void bsm_h_kernel(
    const float* __restrict__ x,
    const float* __restrict__ y,
    const float* __restrict__ win)
{
    const int tid = threadIdx.x;
    const int img = blockIdx.y;
    const int b   = img / CH;
    const int r0  = blockIdx.x * 4;

    __shared__ float2 sxy[4][268];
    __shared__ float g1[16];
    __shared__ double sred[8];

    // Separable 1D gaussian = row sums of the 2D window (sum(g)=1).
    if (tid < KS) {
        float s = 0.f;
        #pragma unroll
        for (int j = 0; j < KS; j++) s += win[tid * KS + j];
        g1[tid] = s;
    }
    // zero halos (image edge -> zero pad)
    if (tid < 5) {
        #pragma unroll
        for (int j = 0; j < 4; j++) {
            sxy[j][tid] = make_float2(0.f, 0.f);
            sxy[j][IMW + 5 + tid] = make_float2(0.f, 0.f);
        }
    }

    const size_t ibase = (size_t)img * (IMH * IMW);
    unsigned int* bhist = &d_hist[b * (NB * NB)];
    float mse_loc = 0.f;

    #pragma unroll
    for (int j = 0; j < 4; j++) {
        size_t base = ibase + (size_t)(r0 + j) * IMW;
        float xv = x[base + tid];
        float yv = y[base + tid];
        sxy[j][5 + tid] = make_float2(xv, yv);

        // MI binning (exact reference op order) + MSE
        float xf = (xv + 1.0f) * 0.5f;
        float yf = (yv + 1.0f) * 0.5f;
        int ix = (int)(xf * 256.0f); ix = min(max(ix, 0), NB - 1);
        int iy = (int)(yf * 256.0f); iy = min(max(iy, 0), NB - 1);
        atomicAdd(&bhist[ix * NB + iy], 1u);
        float d = (xv * 0.5f + 0.5f) - (yv * 0.5f + 0.5f);
        mse_loc = fmaf(d, d, mse_loc);
    }
    __syncthreads();

    // hoist weights into registers (11 LDS once instead of 44 in-loop reads)
    float wreg[KS];
    #pragma unroll
    for (int k = 0; k < KS; k++) wreg[k] = g1[k];

    #pragma unroll
    for (int j = 0; j < 4; j++) {
        float a0 = 0.f, a1 = 0.f, a2 = 0.f, a3 = 0.f, a4 = 0.f;
        #pragma unroll
        for (int k = 0; k < KS; k++) {
            float w  = wreg[k];
            float2 v = sxy[j][tid + k];     // one LDS.64
            a0 = fmaf(w, v.x, a0);
            a1 = fmaf(w, v.y, a1);
            a2 = fmaf(w, v.x * v.x, a2);
            a3 = fmaf(w, v.y * v.y, a3);
            a4 = fmaf(w, v.x * v.y, a4);
        }
        size_t o = ibase + (size_t)(r0 + j) * IMW + tid;
        d_f01[o] = __floats2half2_rn(a0, a1);
        d_f23[o] = __floats2half2_rn(a2, a3);
        d_f4[o]  = __float2half_rn(a4);
    }

    // block reduce mse -> one double atomic
    #pragma unroll
    for (int off = 16; off; off >>= 1)
        mse_loc += __shfl_down_sync(0xffffffffu, mse_loc, off);
    int lane = tid & 31, warp = tid >> 5;
    if (lane == 0) sred[warp] = (double)mse_loc;
    __syncthreads();
    if (tid == 0) {
        double m = 0.0;
        #pragma unroll
        for (int w = 0; w < 8; w++) m += sred[w];
        atomicAdd(&d_mse_sum[b], m);
    }
}

// ---------------------------------------------------------------------------
// K_V body, templated on GUARD. Interior row-tiles (blockIdx.y 1..6) never
// touch rows outside [0,256) — they take the branch-free path.
// ---------------------------------------------------------------------------
template <bool GUARD>
__device__ __forceinline__ float bsm_v_body(
    const float* __restrict__ wreg, int col, int r0, size_t ibase)
{
    float mu1[4], mu2[4], m11[4], m22[4], m12[4];

    // fields 0,1 (mu1, mu2)
    {
        float2 v[14];
        #pragma unroll
        for (int t = 0; t < 14; t++) {
            int rr = r0 + t - RAD;
            if (GUARD) {
                v[t] = (rr >= 0 && rr < IMH)
                     ? __half22float2(d_f01[ibase + (size_t)rr * IMW + col])
                     : make_float2(0.f, 0.f);
            } else {
                v[t] = __half22float2(d_f01[ibase + (size_t)rr * IMW + col]);
            }
        }
        #pragma unroll
        for (int j = 0; j < 4; j++) { mu1[j] = 0.f; mu2[j] = 0.f; }
        #pragma unroll
        for (int k = 0; k < KS; k++) {
            float w = wreg[k];
            #pragma unroll
            for (int j = 0; j < 4; j++) {
                mu1[j] = fmaf(w, v[j + k].x, mu1[j]);
                mu2[j] = fmaf(w, v[j + k].y, mu2[j]);
            }
        }
    }
    // fields 2,3 (m11, m22)
    {
        float2 v[14];
        #pragma unroll
        for (int t = 0; t < 14; t++) {
            int rr = r0 + t - RAD;
            if (GUARD) {
                v[t] = (rr >= 0 && rr < IMH)
                     ? __half22float2(d_f23[ibase + (size_t)rr * IMW + col])
                     : make_float2(0.f, 0.f);
            } else {
                v[t] = __half22float2(d_f23[ibase + (size_t)rr * IMW + col]);
            }
        }
        #pragma unroll
        for (int j = 0; j < 4; j++) { m11[j] = 0.f; m22[j] = 0.f; }
        #pragma unroll
        for (int k = 0; k < KS; k++) {
            float w = wreg[k];
            #pragma unroll
            for (int j = 0; j < 4; j++) {
                m11[j] = fmaf(w, v[j + k].x, m11[j]);
                m22[j] = fmaf(w, v[j + k].y, m22[j]);
            }
        }
    }
    // field 4 (m12)
    {
        float v[14];
        #pragma unroll
        for (int t = 0; t < 14; t++) {
            int rr = r0 + t - RAD;
            if (GUARD) {
                v[t] = (rr >= 0 && rr < IMH)
                     ? __half2float(d_f4[ibase + (size_t)rr * IMW + col]) : 0.f;
            } else {
                v[t] = __half2float(d_f4[ibase + (size_t)rr * IMW + col]);
            }
        }
        #pragma unroll
        for (int j = 0; j < 4; j++) m12[j] = 0.f;
        #pragma unroll
        for (int k = 0; k < KS; k++) {
            float w = wreg[k];
            #pragma unroll
            for (int j = 0; j < 4; j++)
                m12[j] = fmaf(w, v[j + k], m12[j]);
        }
    }

    const float C1c = 0.01f * 0.01f;
    const float C2c = 0.03f * 0.03f;
    float ssim_loc = 0.f;
    #pragma unroll
    for (int j = 0; j < 4; j++) {
        float mu1s = mu1[j] * mu1[j];
        float mu2s = mu2[j] * mu2[j];
        float mu12 = mu1[j] * mu2[j];
        float s1  = m11[j] - mu1s;
        float s2  = m22[j] - mu2s;
        float s12 = m12[j] - mu12;
        float num = (2.f * mu12 + C1c) * (2.f * s12 + C2c);
        float den = (mu1s + mu2s + C1c) * (s1 + s2 + C2c);
        ssim_loc += num / den;
    }
    return ssim_loc;
}

// ---------------------------------------------------------------------------
// Kernel 2 (K_V): vertical 11-tap pass + SSIM formula + reduction.
// block = 256 threads = 32 cols x 8 row-groups; each row-group -> 4 rows.
// grid = (IMW/32, IMH/32, NIMG). Interior tiles take a branch-free path.
// ---------------------------------------------------------------------------
__global__ __launch_bounds__(256) void bsm_v_kernel(const float* __restrict__ win)
{
    const int tid = threadIdx.x;
    const int img = blockIdx.z;
    const int b   = img / CH;

    __shared__ float g1[16];
    __shared__ double sred[8];

    if (tid < KS) {
        float s = 0.f;
        #pragma unroll
        for (int j = 0; j < KS; j++) s += win[tid * KS + j];
        g1[tid] = s;
    }
    __syncthreads();

    // hoist weights into registers
    float wreg[KS];
    #pragma unroll
    for (int k = 0; k < KS; k++) wreg[k] = g1[k];

    const int c   = tid & 31;
    const int col = blockIdx.x * 32 + c;
    const int r0  = blockIdx.y * 32 + (tid >> 5) * 4;
    const size_t ibase = (size_t)img * (IMH * IMW);

    float ssim_loc;
    if (blockIdx.y == 0 || blockIdx.y == gridDim.y - 1)
        ssim_loc = bsm_v_body<true >(wreg, col, r0, ibase);
    else
        ssim_loc = bsm_v_body<false>(wreg, col, r0, ibase);

    #pragma unroll
    for (int off = 16; off; off >>= 1)
        ssim_loc += __shfl_down_sync(0xffffffffu, ssim_loc, off);
    int lane = tid & 31, warp = tid >> 5;
    if (lane == 0) sred[warp] = (double)ssim_loc;
    __syncthreads();
    if (tid == 0) {
        double s = 0.0;
        #pragma unroll
        for (int w = 0; w < 8; w++) s += sred[w];
        atomicAdd(&d_ssim_sum[b], s);
    }
}

// ---------------------------------------------------------------------------
// Kernel 3a: histogram scan — coalesced uint4 reads, self-cleaning.
// Runs on a SIDE STREAM concurrent with K_V (depends only on d_hist).
// grid = (8 chunks, 64 batches), block = 256 (8 warps, warp -> 4 rows).
// ---------------------------------------------------------------------------
__global__ __launch_bounds__(256) void bsm_fin_a_kernel()
{
    const int b     = blockIdx.y;
    const int chunk = blockIdx.x;
    const int tid   = threadIdx.x;
    const int lane  = tid & 31;
    const int warp  = tid >> 5;

    __shared__ unsigned int spy[NB];
    __shared__ double sredA[8], sredB[8];

    spy[tid] = 0u;
    __syncthreads();

    uint4* hb4 = (uint4*)&d_hist[b * NB * NB];
    const float invNf = 1.0f / (float)NPIX;
    const uint4 z4 = make_uint4(0u, 0u, 0u, 0u);

    double hxy_loc = 0.0;
    double hx_loc  = 0.0;

    // warp handles 4 consecutive rows
    #pragma unroll
    for (int rr = 0; rr < 4; rr++) {
        int row = chunk * 32 + warp * 4 + rr;
        uint4 q0 = hb4[row * 64 + lane];
        uint4 q1 = hb4[row * 64 + 32 + lane];
        hb4[row * 64 + lane] = z4;          // self-clean for next launch
        hb4[row * 64 + 32 + lane] = z4;
        unsigned int cs[8] = {q0.x, q0.y, q0.z, q0.w, q1.x, q1.y, q1.z, q1.w};

        unsigned int px_part = 0;
        float h_part = 0.f;      // Σ -p*log2(p) over this lane's 8 bins
        #pragma unroll
        for (int k = 0; k < 8; k++) {
            unsigned int cnt = cs[k];
            px_part += cnt;
            if (cnt) {
                float p = (float)cnt * invNf;
                h_part -= p * __log2f(p);
                int colk = (k < 4) ? (lane * 4 + k) : (128 + lane * 4 + (k - 4));
                atomicAdd(&spy[colk], cnt);
            }
        }
        hxy_loc += (double)h_part;

        #pragma unroll
        for (int off = 16; off; off >>= 1)
            px_part += __shfl_down_sync(0xffffffffu, px_part, off);
        if (lane == 0 && px_part) {
            float pxn = (float)px_part * invNf;
            hx_loc -= (double)(pxn * __log2f(pxn));
        }
    }

    #pragma unroll
    for (int off = 16; off; off >>= 1)
        hxy_loc += __shfl_down_sync(0xffffffffu, hxy_loc, off);
    if (lane == 0) { sredA[warp] = hxy_loc; sredB[warp] = hx_loc; }
    __syncthreads();
    if (tid == 0) {
        double a = 0.0, bb = 0.0;
        #pragma unroll
        for (int w = 0; w < 8; w++) { a += sredA[w]; bb += sredB[w]; }
        atomicAdd(&d_hxy[b], a);
        atomicAdd(&d_hx[b],  bb);
    }
    __syncthreads();
    if (spy[tid]) atomicAdd(&d_py[b * NB + tid], spy[tid]);
}

// ---------------------------------------------------------------------------
// Kernel 3b: combine — H(Y) from d_py, final MI/SSIM/PSNR, write out.
// Warp-shuffle reduction; self-cleaning. Runs at the stream join.
// ---------------------------------------------------------------------------
__global__ __launch_bounds__(256) void bsm_fin_b_kernel(float* __restrict__ out)
{
    const int b    = blockIdx.x;
    const int t    = threadIdx.x;
    const int lane = t & 31;
    const int warp = t >> 5;
    const float invNf = 1.0f / (float)NPIX;
    const double invN = 1.0 / (double)NPIX;

    __shared__ double shy[8];

    unsigned int py = d_py[b * NB + t];
    d_py[b * NB + t] = 0u;                   // self-clean
    float pyn = (float)py * invNf;
    double hy_loc = (py > 0) ? (double)(-pyn * __log2f(pyn)) : 0.0;
    #pragma unroll
    for (int off = 16; off; off >>= 1)
        hy_loc += __shfl_down_sync(0xffffffffu, hy_loc, off);
    if (lane == 0) shy[warp] = hy_loc;
    __syncthreads();

    if (t == 0) {
        double hy = 0.0;
        #pragma unroll
        for (int w = 0; w < 8; w++) hy += shy[w];

        double hx = d_hx[b], hxyv = d_hxy[b];
        double ssim_s = d_ssim_sum[b];
        double mse_s  = d_mse_sum[b];
        d_hx[b] = 0.0; d_hxy[b] = 0.0;       // self-clean
        d_ssim_sum[b] = 0.0; d_mse_sum[b] = 0.0;

        double mi = hx + hy - hxyv;
        double norm = fmin(hx, hy);
        mi = (norm > 0.0) ? (mi / norm) : 0.0;
        mi = fmin(fmax(mi, 0.0), 1.0);

        double ssim = ssim_s * invN;

        double mse = mse_s * invN;
        double psnr = (mse == 0.0) ? 100.0 : (-10.0 * log10(mse));
        psnr /= 40.0;

        out[b * 3 + 0] = (float)mi;
        out[b * 3 + 1] = (float)ssim;
        out[b * 3 + 2] = (float)psnr;
    }
}

// ---------------------------------------------------------------------------
// Launch topology (round-14 fork-join, measured best):
//   stream0: K_H ──evA──────────── K_V ────────┬── fin_b
//   side:         └─(wait evA) fin_a ───evB────┘
// ---------------------------------------------------------------------------
extern "C" void kernel_launch(void* const* d_in, const int* in_sizes, int n_in,
                              void* d_out, int out_size)
{
    const float* x   = (const float*)d_in[0];
    const float* y   = (const float*)d_in[1];
    const float* win = (const float*)d_in[2];
    float* out = (float*)d_out;

    static cudaStream_t s_side = nullptr;
    static cudaEvent_t  evA = nullptr, evB = nullptr;
    if (s_side == nullptr) {
        cudaStreamCreateWithFlags(&s_side, cudaStreamNonBlocking);
        cudaEventCreateWithFlags(&evA, cudaEventDisableTiming);
        cudaEventCreateWithFlags(&evB, cudaEventDisableTiming);
    }

    dim3 gh(IMH / 4, NIMG);
    bsm_h_kernel<<<gh, 256>>>(x, y, win);

    // fork: fin_a on side stream, concurrent with K_V
    cudaEventRecord(evA, 0);
    cudaStreamWaitEvent(s_side, evA, 0);
    dim3 gf(8, BATCH);
    bsm_fin_a_kernel<<<gf, 256, 0, s_side>>>();

    dim3 gv(IMW / 32, IMH / 32, NIMG);
    bsm_v_kernel<<<gv, 256>>>(win);

    // join: fin_b needs fin_a (hx/hxy/py) and K_V (ssim) and K_H (mse)
    cudaEventRecord(evB, s_side);
    cudaStreamWaitEvent(0, evB, 0);
    bsm_fin_b_kernel<<<BATCH, 256>>>(out);
}